// round 13
// baseline (speedup 1.0000x reference)
#include <cuda_runtime.h>

// Radon forward projection: quad-stencil tile + XOR bank swizzle, single launch.
// out[b,a,s] = sum_t bilinear(imgs[b], x(s,t), y(s,t)),
// x = s*cos - t*sin + c ; y = s*sin + t*cos + c ; c = 127.5.
//
// Block = (b, angle-pair, phase), 12,960 blocks, 512 threads (2 angles x 256
// detectors). Phase p owns y0i in a 15-row band (16 for p0). Tile element
// (r, c) is a float4 QUAD (a00,a01,a10,a11) covering rows (base+r, base+r+1),
// cols (c-5, c-4): the whole bilinear stencil in ONE LDS.128 per sample.
// Columns are XOR-swizzled: pos = r*288 + (c ^ ((yi<<1)&6)) with yi = 15p+r,
// so diagonal rays (the measured ~3x bank-conflict replay case, L1=66%) are
// conflict-free; worst residual is 2-way on vertical rays.
// 16 x 288 x 16B = 73.7 KB smem -> 3 CTAs/SM.
//
// Ownership is EXACT and unchanged: band p owns yv = y+1 in [lo_p, hi_p),
// integer float bounds, tested on the SAME fmaf(tf,ca,ys1) everywhere;
// monotone yv(t): conservative analytic entry/exit + exact scans -> counted
// branchless loop; exit-scan start clamped to txhi+1 so all counted
// iterations are in-band AND in-window. Guard-shifted coords xv=x+5, yv=y+1.
//
// Fused reduction: 720 (b,pair) groups x 18 phase blocks; last block of each
// group (atomic ticket, self-resetting) sums partials in fixed p-order.

#define B_ 8
#define N_ 256
#define A_ 180

constexpr int PAIRS      = A_ / 2;            // 90
constexpr int BAND       = 15;
constexpr int PHASES     = 18;                // 15*17+16 = 271 >= 258
constexpr int QSTRIDE    = 288;               // quads per tile row (0 mod 8)
constexpr int TROWS      = 16;                // quad rows: covers BAND+1 rows
constexpr int SMEM_BYTES = TROWS * QSTRIDE * 16;  // 73,728 B -> 3 CTAs/SM
constexpr int NGROUP     = B_ * PAIRS;            // 720
constexpr int NBLK       = NGROUP * PHASES;       // 12,960

__device__ float g_partial[NBLK * 512];       // 26.5 MB static scratch
__device__ int   g_ticket[NGROUP];            // zero-init; self-resetting

// ---- packed f32x2 helpers (sm_103a FFMA2/FADD2 via PTX) ----
typedef unsigned long long u64;
__device__ __forceinline__ u64 pk2(float lo, float hi) {
    u64 r; asm("mov.b64 %0, {%1, %2};" : "=l"(r) : "f"(lo), "f"(hi)); return r;
}
__device__ __forceinline__ void upk2(u64 v, float& lo, float& hi) {
    asm("mov.b64 {%0, %1}, %2;" : "=f"(lo), "=f"(hi) : "l"(v));
}
__device__ __forceinline__ u64 fma2(u64 a, u64 b, u64 c) {
    u64 d; asm("fma.rn.f32x2 %0, %1, %2, %3;" : "=l"(d) : "l"(a), "l"(b), "l"(c));
    return d;
}
__device__ __forceinline__ u64 add2(u64 a, u64 b) {
    u64 d; asm("add.rn.f32x2 %0, %1, %2;" : "=l"(d) : "l"(a), "l"(b));
    return d;
}

// Store partial; group's LAST block reduces the 18 partials in fixed p-order.
__device__ __forceinline__ void finalize_group(
    float acc, int bp, int tid, float* __restrict__ out)
{
    __shared__ int is_last;
    const int blk0 = bp * PHASES;
    g_partial[(blk0 + (blockIdx.x % PHASES)) * 512 + tid] = acc;
    __threadfence();
    __syncthreads();
    if (tid == 0) {
        int prev = atomicAdd(&g_ticket[bp], 1);
        is_last = (prev == PHASES - 1);
    }
    __syncthreads();
    if (!is_last) return;

    __threadfence();
    const float* p = g_partial + blk0 * 512 + tid;
    float sum = 0.0f;
    #pragma unroll
    for (int k = 0; k < PHASES; ++k) sum += p[k * 512];   // fixed order
    out[bp * 512 + tid] = sum;
    if (tid == 0) g_ticket[bp] = 0;           // reset for next graph replay
}

__global__ __launch_bounds__(512, 3)
void radon_phase_kernel(const float* __restrict__ imgs,
                        const float* __restrict__ angles,
                        float* __restrict__ out)
{
    extern __shared__ float4 tile4[];

    const int tid  = threadIdx.x;
    const int blk  = blockIdx.x;
    const int p    = blk % PHASES;
    const int bp   = blk / PHASES;            // b*PAIRS + pair
    const int b    = bp / PAIRS;
    const int pr   = bp - b * PAIRS;
    const int al   = tid >> 8;                // which angle of the pair
    const int warp = tid >> 5;                // 16 warps == 16 quad rows
    const int lane = tid & 31;

    const float ang = angles[pr * 2 + al];
    const float ca  = cosf(ang);
    const float sa  = sinf(ang);
    const float sf  = (float)(tid & 255) - 127.5f;
    const float xs  = fmaf(sf, ca, 127.5f);
    const float xs5 = xs + 5.0f;              // guard-shifted x origin
    const float ys1 = fmaf(sf, sa, 127.5f) + 1.0f;   // guard-shifted y origin
    const float nsa = -sa;
    const bool  up  = (ca >= 0.0f);           // yv non-decreasing in t?

    // yv endpoints (same fmaf form as the loop) for exact band pre-check
    const float yA    = fmaf(-127.5f, ca, ys1);
    const float yB    = fmaf( 127.5f, ca, ys1);
    const float yvmin = fminf(yA, yB);
    const float yvmax = fmaxf(yA, yB);

    // Owned band: floor(yv) in [lo, hi-1].
    // p=0: y0i in [-1,14] -> yv in [0,16).
    // p>0: y0i in [15p, 15p+14] -> yv in [15p+1, 15p+16). Exact int bounds.
    const float lo = (p == 0) ? 0.0f : (float)(BAND * p + 1);
    const float hi = (float)(BAND * p + 16);

    // block-wide empty-band early out (skip staging entirely)
    const bool hit = (yvmax >= lo) & (yvmin < hi);
    if (!__syncthreads_or(hit)) {
        finalize_group(0.0f, bp, tid, out);
        return;
    }

    // ---- stage quad tile: warp r stages quad row r.
    // quad(r,c) = (img[y0][c-5], img[y0][c-4], img[y0+1][c-5], img[y0+1][c-4])
    // stored at column (c ^ key_r), key_r = ((15p+r)<<1)&6 (yi of this row).
    {
        const int r    = warp;
        const int y0   = BAND * p - 1 + r;    // top image row of quad row r
        const bool y0ok = (unsigned)y0       < (unsigned)N_;
        const bool y1ok = (unsigned)(y0 + 1) < (unsigned)N_;
        const float* __restrict__ s0 = imgs + b * N_ * N_ + y0 * N_;
        const float* __restrict__ s1 = s0 + N_;
        const int key = ((BAND * p + r) << 1) & 6;
        float4* dst = tile4 + r * QSTRIDE;
        for (int c = lane; c < QSTRIDE; c += 32) {
            int ic = c - 5;
            bool c0 = (unsigned)ic       < (unsigned)N_;
            bool c1 = (unsigned)(ic + 1) < (unsigned)N_;
            float4 q;
            q.x = (y0ok && c0) ? s0[ic]     : 0.0f;
            q.y = (y0ok && c1) ? s0[ic + 1] : 0.0f;
            q.z = (y1ok && c0) ? s1[ic]     : 0.0f;
            q.w = (y1ok && c1) ? s1[ic + 1] : 0.0f;
            dst[c ^ key] = q;
        }
    }
    __syncthreads();

    float acc = 0.0f;

    if (hit) {
        // analytic helpers (conservative only; exactness from scans)
        const float inv_ca = 1.0f / ((ca == 0.0f) ? 1e-30f : ca);
        const float inv_sa = 1.0f / ((sa == 0.0f) ? 1e-30f : sa);

        // x-window: x outside (-3,259) padded +-2 -> sampled cols are zero
        // guards -> exactly 0. Inside: xv = x+5 in (-0.01, 266.01).
        float tca = (xs + 3.0f)   * inv_sa;
        float tcb = (xs - 259.0f) * inv_sa;
        const int txlo = (int)fmaxf(floorf(fminf(tca, tcb) + 127.5f) - 2.0f, 0.0f);
        const int txhi = (int)fminf(ceilf (fmaxf(tca, tcb) + 127.5f) + 2.0f, 255.0f);

        // conservative analytic entry (pad -2, never late), exact entry scan
        const float Lb = up ? lo : hi;
        float t_ent = fmaf(Lb - ys1, inv_ca, 127.5f);
        int t = max((int)fmaxf(fminf(floorf(t_ent) - 2.0f, 255.0f), 0.0f), txlo);
        float tf = (float)t - 127.5f;
        for (; t <= txhi; ++t, tf += 1.0f) {
            float yv = fmaf(tf, ca, ys1);
            if (up ? (yv >= lo) : (yv < hi)) break;
        }

        int n = 0;
        if (t <= txhi) {
            // conservative analytic exit, exact exit scan; start clamped to
            // txhi+1 (in float, before the int cast) so window-limited rays
            // count exactly txhi+1-t iterations (R8 fix).
            const float Ub = up ? hi : lo;
            float t_xt = fmaf(Ub - ys1, inv_ca, 127.5f);
            float te_f = fmaxf(fminf(floorf(t_xt) - 2.0f, (float)(txhi + 1)),
                               (float)t);
            int te = (int)te_f;
            float tfe = (float)te - 127.5f;
            for (; te <= txhi; ++te, tfe += 1.0f) {
                float yv = fmaf(tfe, ca, ys1);
                if (up ? (yv >= hi) : (yv < lo)) break;   // first t past band
            }
            n = te - t;     // owned iterations: t .. te-1 (in-band, in-window)
        }

        // fold band row offset: row = yi - 15p; element = row*288 + xsw
        const float4* __restrict__ tbq = tile4 - (BAND * p) * QSTRIDE;

        const u64 CANSA = pk2(ca, nsa);       // (ca, -sa)
        const u64 YXS   = pk2(ys1, xs5);      // (y origin, x origin)
        const u64 ONE2  = pk2(1.0f, 1.0f);
        const u64 NEG1  = pk2(-1.0f, -1.0f);
        u64 tf2 = pk2(tf, tf);

        #pragma unroll 4
        for (int k = 0; k < n; ++k) {
            u64 yx = fma2(tf2, CANSA, YXS);   // (yv, xv) — bitwise == scalar
            float yv, xv; upk2(yx, yv, xv);
            float fy = truncf(yv);            // yv >= 0 in-band: trunc == floor
            float fx = truncf(xv);            // eps<0 -> col 0 zero guard
            u64 wyx = fma2(pk2(fy, fx), NEG1, yx);   // (wy, wx), exact
            float wy, wx; upk2(wyx, wy, wx);

            int yi  = (int)fy;
            int xi  = (int)fx;
            int xsw = xi ^ ((yi << 1) & 6);   // bank swizzle (SHF+LOP3)
            const float4 q = tbq[yi * QSTRIDE + xsw];   // one LDS.128

            float h0 = fmaf(wx, q.y - q.x, q.x);
            float h1 = fmaf(wx, q.w - q.z, q.z);
            acc += fmaf(wy, h1 - h0, h0);

            tf2 = add2(tf2, ONE2);
        }
    }

    finalize_group(acc, bp, tid, out);
}

extern "C" void kernel_launch(void* const* d_in, const int* in_sizes, int n_in,
                              void* d_out, int out_size)
{
    const float* imgs   = (const float*)d_in[0];
    const float* angles = (const float*)d_in[1];
    float*       out    = (float*)d_out;

    cudaFuncSetAttribute(radon_phase_kernel,
                         cudaFuncAttributeMaxDynamicSharedMemorySize, SMEM_BYTES);

    radon_phase_kernel<<<NBLK, 512, SMEM_BYTES>>>(imgs, angles, out);
}

// round 14
// speedup vs baseline: 1.3904x; 1.3904x over previous
#include <cuda_runtime.h>

// Radon forward projection, phase-split + row-pair-float2 + XOR bank swizzle.
// out[b,a,s] = sum_t bilinear(imgs[b], x(s,t), y(s,t)),
// x = s*cos - t*sin + c ; y = s*sin + t*cos + c ; c = 127.5.
//
// Kernel 1: block = (b, angle-pair, phase), 6480 blocks, 512 threads
// (2 angles x 256 detectors). Phase p owns y0i in a 31-row band (32 for p0).
// Tile rows are float2 ROW PAIRS: element (r, c) = (img[base+r][c-5],
// img[base+r+1][c-5]) -> 2x LDS.64 per bilinear sample.
//
// CONFLICT FIX (the R12 profile showed L1=66% = ~3.7x replay; conflict-free
// floor is ~18%): row stride 288 float2 (== 0 mod 16) makes the bank-pair
// index xsw mod 16, and each element is stored at swizzled column
// c ^ (yi & 15) where yi = global tile-row label (31p + r). Vertical rays:
// 16 distinct keys -> conflict-free. Horizontal: xi steps -> free. Diagonal
// (the old 16-way case): XOR of co-stepping counters -> ~2-way worst.
// Readers address BOTH x-neighbors explicitly: (xi)^key and (xi+1)^key
// (adjacency does not survive the swizzle — R13 lesson).
// 32 x 288 x 8B = 73,728 B dynamic smem -> 3 CTAs/SM.
//
// Ownership is EXACT (unchanged since R8): band p owns yv = y+1 in
// [lo_p, hi_p), integer float bounds, tested on the SAME fmaf(tf,ca,ys1)
// everywhere; monotone yv(t): conservative analytic entry/exit + exact scans
// -> branchless counted loop; exit-scan start clamped to txhi+1 so all
// counted iterations are in-band AND in-window (every smem access staged).
// Guard-shifted coords xv = x+5 (trunc; eps<0 -> zero guard cols), yv = y+1.

#define B_ 8
#define N_ 256
#define A_ 180

constexpr int PAIRS      = A_ / 2;            // 90
constexpr int BAND       = 31;
constexpr int PHASES     = 9;                 // ceil(257/31)
constexpr int STRIDE     = 288;               // float2 elements per tile row
constexpr int TROWS      = 32;                // row-pairs: covers BAND+1 rows
constexpr int SMEM_BYTES = TROWS * STRIDE * 8;    // 73,728 B -> 3 CTAs/SM
constexpr int NBLK       = B_ * PAIRS * PHASES;   // 6480

__device__ float g_partial[NBLK * 512];       // 13.3 MB static scratch

// ---- packed f32x2 helpers (sm_103a FFMA2/FADD2 via PTX) ----
typedef unsigned long long u64;
__device__ __forceinline__ u64 pk2(float lo, float hi) {
    u64 r; asm("mov.b64 %0, {%1, %2};" : "=l"(r) : "f"(lo), "f"(hi)); return r;
}
__device__ __forceinline__ void upk2(u64 v, float& lo, float& hi) {
    asm("mov.b64 {%0, %1}, %2;" : "=f"(lo), "=f"(hi) : "l"(v));
}
__device__ __forceinline__ u64 fma2(u64 a, u64 b, u64 c) {
    u64 d; asm("fma.rn.f32x2 %0, %1, %2, %3;" : "=l"(d) : "l"(a), "l"(b), "l"(c));
    return d;
}
__device__ __forceinline__ u64 add2(u64 a, u64 b) {
    u64 d; asm("add.rn.f32x2 %0, %1, %2;" : "=l"(d) : "l"(a), "l"(b));
    return d;
}

__global__ __launch_bounds__(512, 3)
void radon_phase_kernel(const float* __restrict__ imgs,
                        const float* __restrict__ angles)
{
    extern __shared__ float2 tile[];

    const int tid  = threadIdx.x;
    const int blk  = blockIdx.x;
    const int p    = blk % PHASES;
    const int bp   = blk / PHASES;            // b*PAIRS + pair
    const int b    = bp / PAIRS;
    const int pr   = bp - b * PAIRS;
    const int al   = tid >> 8;                // which angle of the pair
    const int warp = tid >> 5;
    const int lane = tid & 31;

    const float ang = angles[pr * 2 + al];
    const float ca  = cosf(ang);
    const float sa  = sinf(ang);
    const float sf  = (float)(tid & 255) - 127.5f;
    const float xs  = fmaf(sf, ca, 127.5f);
    const float xs5 = xs + 5.0f;              // guard-shifted x origin
    const float ys1 = fmaf(sf, sa, 127.5f) + 1.0f;   // guard-shifted y origin
    const float nsa = -sa;
    const bool  up  = (ca >= 0.0f);           // yv non-decreasing in t?

    // yv endpoints (same fmaf form as the loop) for exact band pre-check
    const float yA    = fmaf(-127.5f, ca, ys1);
    const float yB    = fmaf( 127.5f, ca, ys1);
    const float yvmin = fminf(yA, yB);
    const float yvmax = fmaxf(yA, yB);

    // Owned band in yv space: floor(yv) in [lo, hi-1].
    // p=0: y0i in [-1,30] -> yv in [0,32).
    // p>0: y0i in [31p, 31p+30] -> yv in [31p+1, 31p+32). Exact int bounds.
    const float lo = (p == 0) ? 0.0f : (float)(BAND * p + 1);
    const float hi = (float)(BAND * p + 32);

    // block-wide empty-band early out (skip staging entirely)
    const bool hit = (yvmax >= lo) & (yvmin < hi);
    if (!__syncthreads_or(hit)) {
        g_partial[blk * 512 + tid] = 0.0f;
        return;
    }

    // ---- stage row-pair tile at swizzled columns: dst col = c ^ (yi & 15),
    // yi = 31p + r (the same label the reader derives as floor(yv)).
    const int base = BAND * p - 1;            // image row of tile row r=0 (.x)
    const float* __restrict__ img = imgs + b * N_ * N_;
    for (int r = warp; r < TROWS; r += 16) {
        const int ir0 = base + r;
        const int ir1 = ir0 + 1;
        const bool v0ok = (unsigned)ir0 < (unsigned)N_;
        const bool v1ok = (unsigned)ir1 < (unsigned)N_;
        const float* s0 = img + ir0 * N_;
        const float* s1 = img + ir1 * N_;
        const int key = (BAND * p + r) & 15;
        float2* dst = tile + r * STRIDE;
        for (int c = lane; c < STRIDE; c += 32) {
            int ic = c - 5;
            bool cin = (unsigned)ic < (unsigned)N_;
            float v0 = (v0ok && cin) ? s0[ic] : 0.0f;
            float v1 = (v1ok && cin) ? s1[ic] : 0.0f;
            dst[c ^ key] = make_float2(v0, v1);
        }
    }
    __syncthreads();

    float acc = 0.0f;

    if (hit) {
        // analytic helpers (conservative only; exactness from scans)
        const float inv_ca = 1.0f / ((ca == 0.0f) ? 1e-30f : ca);
        const float inv_sa = 1.0f / ((sa == 0.0f) ? 1e-30f : sa);

        // x-window: x outside (-3,259) padded +-2 -> sampled cols are zero
        // guards -> exactly 0. Inside: xv = x+5 in (-0.01, 266.01), so
        // xi in [0,266], xi+1 <= 267 < 288: all staged.
        float tca = (xs + 3.0f)   * inv_sa;
        float tcb = (xs - 259.0f) * inv_sa;
        const int txlo = (int)fmaxf(floorf(fminf(tca, tcb) + 127.5f) - 2.0f, 0.0f);
        const int txhi = (int)fminf(ceilf (fmaxf(tca, tcb) + 127.5f) + 2.0f, 255.0f);

        // conservative analytic entry (pad -2, never late), exact entry scan
        const float Lb = up ? lo : hi;
        float t_ent = fmaf(Lb - ys1, inv_ca, 127.5f);
        int t = max((int)fmaxf(fminf(floorf(t_ent) - 2.0f, 255.0f), 0.0f), txlo);
        float tf = (float)t - 127.5f;
        for (; t <= txhi; ++t, tf += 1.0f) {
            float yv = fmaf(tf, ca, ys1);
            if (up ? (yv >= lo) : (yv < hi)) break;
        }

        int n = 0;
        if (t <= txhi) {
            // conservative analytic exit, exact exit scan; start clamped to
            // txhi+1 (in float, before the int cast) so window-limited rays
            // count exactly txhi+1-t iterations (R8 fix).
            const float Ub = up ? hi : lo;
            float t_xt = fmaf(Ub - ys1, inv_ca, 127.5f);
            float te_f = fmaxf(fminf(floorf(t_xt) - 2.0f, (float)(txhi + 1)),
                               (float)t);
            int te = (int)te_f;
            float tfe = (float)te - 127.5f;
            for (; te <= txhi; ++te, tfe += 1.0f) {
                float yv = fmaf(tfe, ca, ys1);
                if (up ? (yv >= hi) : (yv < lo)) break;   // first t past band
            }
            n = te - t;     // owned iterations: t .. te-1 (in-band, in-window)
        }

        // fold band row offset into the base pointer: tile row = yi - 31p
        const u64* __restrict__ tb64 =
            reinterpret_cast<const u64*>(tile) - (BAND * p) * STRIDE;

        const u64 CANSA = pk2(ca, nsa);       // (ca, -sa)
        const u64 YXS   = pk2(ys1, xs5);      // (y origin, x origin)
        const u64 ONE2  = pk2(1.0f, 1.0f);
        const u64 NEG1  = pk2(-1.0f, -1.0f);
        u64 tf2 = pk2(tf, tf);

        #pragma unroll 4
        for (int k = 0; k < n; ++k) {
            u64 yx = fma2(tf2, CANSA, YXS);   // (yv, xv) — bitwise == scalar
            float yv, xv; upk2(yx, yv, xv);
            float fy = truncf(yv);            // yv >= 0 in-band: trunc == floor
            float fx = truncf(xv);            // eps<0 -> col 0 zero guard
            u64 wyx = fma2(pk2(fy, fx), NEG1, yx);   // (wy, wx), exact
            float wy, wx; upk2(wyx, wy, wx);

            int yi  = (int)fy;
            int xi  = (int)fx;
            int key = yi & 15;
            int row = yi * STRIDE;
            u64 v0 = tb64[row + (xi ^ key)];         // (a00, a10)
            u64 v1 = tb64[row + ((xi + 1) ^ key)];   // (a01, a11)

            u64 d = fma2(v0, NEG1, v1);       // (a01-a00, a11-a10)
            u64 h = fma2(pk2(wx, wx), d, v0); // (h0, h1)
            float h0, h1; upk2(h, h0, h1);
            acc += fmaf(wy, h1 - h0, h0);

            tf2 = add2(tf2, ONE2);
        }
    }

    g_partial[blk * 512 + tid] = acc;
}

// Kernel 2: out[b, 2*pr+al, s] = sum_p partial[((b*90+pr)*9+p)*512 + al*256 + s]
__global__ __launch_bounds__(256)
void radon_reduce_kernel(float* __restrict__ out)
{
    const int o  = blockIdx.x * 256 + threadIdx.x;   // 368,640 outputs
    const int s  = o & 255;
    const int ba = o >> 8;
    const int a  = ba % A_;
    const int b  = ba / A_;
    const int pr = a >> 1;
    const int al = a & 1;

    const float* p = g_partial + ((b * PAIRS + pr) * PHASES) * 512 + al * 256 + s;
    float acc = 0.0f;
    #pragma unroll
    for (int k = 0; k < PHASES; ++k) acc += p[k * 512];
    out[o] = acc;
}

extern "C" void kernel_launch(void* const* d_in, const int* in_sizes, int n_in,
                              void* d_out, int out_size)
{
    const float* imgs   = (const float*)d_in[0];
    const float* angles = (const float*)d_in[1];
    float*       out    = (float*)d_out;

    cudaFuncSetAttribute(radon_phase_kernel,
                         cudaFuncAttributeMaxDynamicSharedMemorySize, SMEM_BYTES);

    radon_phase_kernel<<<NBLK, 512, SMEM_BYTES>>>(imgs, angles);
    radon_reduce_kernel<<<(B_ * A_ * N_) / 256, 256>>>(out);
}

// round 15
// speedup vs baseline: 1.4332x; 1.0308x over previous
#include <cuda_runtime.h>

// Radon forward projection, phase-split + row-pair-float2 + PER-BLOCK STRIDE.
// out[b,a,s] = sum_t bilinear(imgs[b], x(s,t), y(s,t)),
// x = s*cos - t*sin + c ; y = s*sin + t*cos + c ; c = 127.5.
//
// Kernel 1: block = (b, angle-pair, phase), 6480 blocks, 512 threads
// (2 angles x 256 detectors). Phase p owns y0i in a 31-row band (32 for p0).
// Tile rows are float2 ROW PAIRS -> 2x LDS.64 per sample. 73.5 KB smem ->
// 3 CTAs/SM. Inner loop identical to the proven R11 kernel.
//
// CONFLICT FIX v2: bank conflicts occur only when the per-lane address step
// d = S*sa + ca is within ~1 of a multiple of 16 (or ~0.5 of 8, ~0.3 of 4
// mod 8) — a sparse, angle-specific set. The row stride S is therefore chosen
// PER BLOCK from {287, 281, 273} (all odd, >= 268 so every accessed column
// (<=267) is staged, <= 287 so the smem allocation fits): each block scores
// both of its angles for each candidate and takes the argmax. The choice is
// block-uniform and deterministic; staging and the reader derive addresses
// from the same stride register, so this is correctness-neutral. The inner
// loop cost is unchanged: idx = (int)fmaf(fy, Sf, fx) merely swaps an
// immediate for a register operand (exact for any integer stride: products
// < 2^24). (R14's XOR swizzle is reverted — it was GF2-degenerate on the
// diagonal: xi ^ (yi&15) collapses to one bank when xi == yi.)
//
// Ownership is EXACT (unchanged since R8): band p owns yv = y+1 in
// [lo_p, hi_p), integer float bounds, tested on the SAME fmaf(tf,ca,ys1)
// everywhere; monotone yv(t): conservative analytic entry/exit + exact scans
// -> branchless counted loop; exit-scan start clamped to txhi+1 so all
// counted iterations are in-band AND in-window (every smem access staged).
// Guard-shifted coords xv = x+5 (trunc; eps<0 -> zero guard cols), yv = y+1.

#define B_ 8
#define N_ 256
#define A_ 180

constexpr int PAIRS      = A_ / 2;            // 90
constexpr int BAND       = 31;
constexpr int PHASES     = 9;                 // ceil(257/31)
constexpr int SMAX       = 287;               // max candidate stride
constexpr int TROWS      = 32;                // row-pairs: covers BAND+1 rows
constexpr int SMEM_BYTES = TROWS * SMAX * 8;  // 73,472 B -> 3 CTAs/SM
constexpr int NBLK       = B_ * PAIRS * PHASES;   // 6480

__device__ float g_partial[NBLK * 512];       // 13.3 MB static scratch

// ---- packed f32x2 helpers (sm_103a FFMA2/FADD2 via PTX) ----
typedef unsigned long long u64;
__device__ __forceinline__ u64 pk2(float lo, float hi) {
    u64 r; asm("mov.b64 %0, {%1, %2};" : "=l"(r) : "f"(lo), "f"(hi)); return r;
}
__device__ __forceinline__ void upk2(u64 v, float& lo, float& hi) {
    asm("mov.b64 {%0, %1}, %2;" : "=f"(lo), "=f"(hi) : "l"(v));
}
__device__ __forceinline__ u64 fma2(u64 a, u64 b, u64 c) {
    u64 d; asm("fma.rn.f32x2 %0, %1, %2, %3;" : "=l"(d) : "l"(a), "l"(b), "l"(c));
    return d;
}
__device__ __forceinline__ u64 add2(u64 a, u64 b) {
    u64 d; asm("add.rn.f32x2 %0, %1, %2;" : "=l"(d) : "l"(a), "l"(b));
    return d;
}

// Bank-conflict badness of stride S for one angle: per-lane address step is
// d = S*sa + ca; small distance to multiples of 16 (full collapse), 8, or
// odd multiples of 4 means high conflict degree. Larger score = better.
__device__ __forceinline__ float stride_score(float S, float sa, float ca) {
    float d  = fmaf(S, sa, ca);
    float u0 = d * (1.0f / 16.0f);
    float d0 = fabsf(u0 - rintf(u0)) * 16.0f;          // dist to 0 mod 16
    float u8 = (d - 8.0f) * (1.0f / 16.0f);
    float d8 = fabsf(u8 - rintf(u8)) * 16.0f;          // dist to 8 mod 16
    float u4 = (d - 4.0f) * (1.0f / 8.0f);
    float d4 = fabsf(u4 - rintf(u4)) * 8.0f;           // dist to 4 mod 8
    return fminf(d0, fminf(1.5f * d8, 3.0f * d4));
}

__global__ __launch_bounds__(512, 3)
void radon_phase_kernel(const float* __restrict__ imgs,
                        const float* __restrict__ angles)
{
    extern __shared__ float2 tile[];

    const int tid  = threadIdx.x;
    const int blk  = blockIdx.x;
    const int p    = blk % PHASES;
    const int bp   = blk / PHASES;            // b*PAIRS + pair
    const int b    = bp / PAIRS;
    const int pr   = bp - b * PAIRS;
    const int al   = tid >> 8;                // which angle of the pair
    const int warp = tid >> 5;
    const int lane = tid & 31;

    // ---- block-uniform stride selection from the pair's two angles ----
    const float angA = angles[pr * 2];
    const float angB = angles[pr * 2 + 1];
    const float saA = sinf(angA), caA = cosf(angA);
    const float saB = sinf(angB), caB = cosf(angB);
    int   S  = 287;
    float bs = fminf(stride_score(287.0f, saA, caA),
                     stride_score(287.0f, saB, caB));
    {
        float sc = fminf(stride_score(281.0f, saA, caA),
                         stride_score(281.0f, saB, caB));
        if (sc > bs) { bs = sc; S = 281; }
        sc = fminf(stride_score(273.0f, saA, caA),
                   stride_score(273.0f, saB, caB));
        if (sc > bs) { bs = sc; S = 273; }
    }
    const float Sf = (float)S;

    const float ca  = al ? caB : caA;
    const float sa  = al ? saB : saA;
    const float sf  = (float)(tid & 255) - 127.5f;
    const float xs  = fmaf(sf, ca, 127.5f);
    const float xs5 = xs + 5.0f;              // guard-shifted x origin
    const float ys1 = fmaf(sf, sa, 127.5f) + 1.0f;   // guard-shifted y origin
    const float nsa = -sa;
    const bool  up  = (ca >= 0.0f);           // yv non-decreasing in t?

    // yv endpoints (same fmaf form as the loop) for exact band pre-check
    const float yA    = fmaf(-127.5f, ca, ys1);
    const float yB    = fmaf( 127.5f, ca, ys1);
    const float yvmin = fminf(yA, yB);
    const float yvmax = fmaxf(yA, yB);

    // Owned band in yv space: floor(yv) in [lo, hi-1].
    // p=0: y0i in [-1,30] -> yv in [0,32).
    // p>0: y0i in [31p, 31p+30] -> yv in [31p+1, 31p+32). Exact int bounds.
    const float lo = (p == 0) ? 0.0f : (float)(BAND * p + 1);
    const float hi = (float)(BAND * p + 32);

    // block-wide empty-band early out (skip staging entirely)
    const bool hit = (yvmax >= lo) & (yvmin < hi);
    if (!__syncthreads_or(hit)) {
        g_partial[blk * 512 + tid] = 0.0f;
        return;
    }

    // ---- stage row-pair tile with runtime stride S:
    // tile[r*S + c] = (img[base+r][c-5], img[base+r+1][c-5])
    const int base = BAND * p - 1;            // image row of tile row r=0 (.x)
    const float* __restrict__ img = imgs + b * N_ * N_;
    for (int r = warp; r < TROWS; r += 16) {
        const int ir0 = base + r;
        const int ir1 = ir0 + 1;
        const bool v0ok = (unsigned)ir0 < (unsigned)N_;
        const bool v1ok = (unsigned)ir1 < (unsigned)N_;
        const float* s0 = img + ir0 * N_;
        const float* s1 = img + ir1 * N_;
        float2* dst = tile + r * S;
        for (int c = lane; c < S; c += 32) {
            int ic = c - 5;
            bool cin = (unsigned)ic < (unsigned)N_;
            float v0 = (v0ok && cin) ? s0[ic] : 0.0f;
            float v1 = (v1ok && cin) ? s1[ic] : 0.0f;
            dst[c] = make_float2(v0, v1);
        }
    }
    __syncthreads();

    float acc = 0.0f;

    if (hit) {
        // analytic helpers (conservative only; exactness from scans)
        const float inv_ca = 1.0f / ((ca == 0.0f) ? 1e-30f : ca);
        const float inv_sa = 1.0f / ((sa == 0.0f) ? 1e-30f : sa);

        // x-window: x outside (-3,259) padded +-2 -> sampled cols are zero
        // guards -> exactly 0. Inside: xv = x+5 in (-0.01, 266.01), so
        // xi in [0,266], xi+1 <= 267 < 273 <= S: all staged.
        float tca = (xs + 3.0f)   * inv_sa;
        float tcb = (xs - 259.0f) * inv_sa;
        const int txlo = (int)fmaxf(floorf(fminf(tca, tcb) + 127.5f) - 2.0f, 0.0f);
        const int txhi = (int)fminf(ceilf (fmaxf(tca, tcb) + 127.5f) + 2.0f, 255.0f);

        // conservative analytic entry (pad -2, never late), exact entry scan
        const float Lb = up ? lo : hi;
        float t_ent = fmaf(Lb - ys1, inv_ca, 127.5f);
        int t = max((int)fmaxf(fminf(floorf(t_ent) - 2.0f, 255.0f), 0.0f), txlo);
        float tf = (float)t - 127.5f;
        for (; t <= txhi; ++t, tf += 1.0f) {
            float yv = fmaf(tf, ca, ys1);
            if (up ? (yv >= lo) : (yv < hi)) break;
        }

        int n = 0;
        if (t <= txhi) {
            // conservative analytic exit, exact exit scan; start clamped to
            // txhi+1 (in float, before the int cast) so window-limited rays
            // count exactly txhi+1-t iterations (R8 fix).
            const float Ub = up ? hi : lo;
            float t_xt = fmaf(Ub - ys1, inv_ca, 127.5f);
            float te_f = fmaxf(fminf(floorf(t_xt) - 2.0f, (float)(txhi + 1)),
                               (float)t);
            int te = (int)te_f;
            float tfe = (float)te - 127.5f;
            for (; te <= txhi; ++te, tfe += 1.0f) {
                float yv = fmaf(tfe, ca, ys1);
                if (up ? (yv >= hi) : (yv < lo)) break;   // first t past band
            }
            n = te - t;     // owned iterations: t .. te-1 (in-band, in-window)
        }

        // fold band row offset into the base pointer: tile row = yi - 31p
        const u64* __restrict__ tb64 =
            reinterpret_cast<const u64*>(tile) - (BAND * p) * S;

        const u64 CANSA = pk2(ca, nsa);       // (ca, -sa)
        const u64 YXS   = pk2(ys1, xs5);      // (y origin, x origin)
        const u64 ONE2  = pk2(1.0f, 1.0f);
        const u64 NEG1  = pk2(-1.0f, -1.0f);
        u64 tf2 = pk2(tf, tf);

        #pragma unroll 4
        for (int k = 0; k < n; ++k) {
            u64 yx = fma2(tf2, CANSA, YXS);   // (yv, xv) — bitwise == scalar
            float yv, xv; upk2(yx, yv, xv);
            float fy = truncf(yv);            // yv >= 0 in-band: trunc == floor
            float fx = truncf(xv);            // eps<0 -> col 0 zero guard
            u64 wyx = fma2(pk2(fy, fx), NEG1, yx);   // (wy, wx), exact
            float wy, wx; upk2(wyx, wy, wx);
            int idx = (int)fmaf(fy, Sf, fx);  // exact (integer prods < 2^24)

            u64 v0 = tb64[idx];               // (a00, a10)
            u64 v1 = tb64[idx + 1];           // (a01, a11)

            u64 d = fma2(v0, NEG1, v1);       // (a01-a00, a11-a10)
            u64 h = fma2(pk2(wx, wx), d, v0); // (h0, h1)
            float h0, h1; upk2(h, h0, h1);
            acc += fmaf(wy, h1 - h0, h0);

            tf2 = add2(tf2, ONE2);
        }
    }

    g_partial[blk * 512 + tid] = acc;
}

// Kernel 2: out[b, 2*pr+al, s] = sum_p partial[((b*90+pr)*9+p)*512 + al*256 + s]
__global__ __launch_bounds__(256)
void radon_reduce_kernel(float* __restrict__ out)
{
    const int o  = blockIdx.x * 256 + threadIdx.x;   // 368,640 outputs
    const int s  = o & 255;
    const int ba = o >> 8;
    const int a  = ba % A_;
    const int b  = ba / A_;
    const int pr = a >> 1;
    const int al = a & 1;

    const float* p = g_partial + ((b * PAIRS + pr) * PHASES) * 512 + al * 256 + s;
    float acc = 0.0f;
    #pragma unroll
    for (int k = 0; k < PHASES; ++k) acc += p[k * 512];
    out[o] = acc;
}

extern "C" void kernel_launch(void* const* d_in, const int* in_sizes, int n_in,
                              void* d_out, int out_size)
{
    const float* imgs   = (const float*)d_in[0];
    const float* angles = (const float*)d_in[1];
    float*       out    = (float*)d_out;

    cudaFuncSetAttribute(radon_phase_kernel,
                         cudaFuncAttributeMaxDynamicSharedMemorySize, SMEM_BYTES);

    radon_phase_kernel<<<NBLK, 512, SMEM_BYTES>>>(imgs, angles);
    radon_reduce_kernel<<<(B_ * A_ * N_) / 256, 256>>>(out);
}

// round 16
// speedup vs baseline: 1.4335x; 1.0002x over previous
#include <cuda_runtime.h>

// Radon forward projection, phase-split + row-pair-float2 + PER-BLOCK STRIDE.
// out[b,a,s] = sum_t bilinear(imgs[b], x(s,t), y(s,t)),
// x = s*cos - t*sin + c ; y = s*sin + t*cos + c ; c = 127.5.
//
// Kernel 1: block = (b, angle-pair, phase), 6480 blocks, 512 threads
// (2 angles x 256 detectors). Phase p owns y0i in a 31-row band (32 for p0).
// Tile rows are float2 ROW PAIRS -> 2x LDS.64 per sample. 73.5 KB smem ->
// 3 CTAs/SM. Inner loop identical to the proven R11 kernel.
//
// CONFLICT FIX v2: bank conflicts occur only when the per-lane address step
// d = S*sa + ca is within ~1 of a multiple of 16 (or ~0.5 of 8, ~0.3 of 4
// mod 8) — a sparse, angle-specific set. The row stride S is therefore chosen
// PER BLOCK from {287, 281, 273} (all odd, >= 268 so every accessed column
// (<=267) is staged, <= 287 so the smem allocation fits): each block scores
// both of its angles for each candidate and takes the argmax. The choice is
// block-uniform and deterministic; staging and the reader derive addresses
// from the same stride register, so this is correctness-neutral. The inner
// loop cost is unchanged: idx = (int)fmaf(fy, Sf, fx) merely swaps an
// immediate for a register operand (exact for any integer stride: products
// < 2^24). (R14's XOR swizzle is reverted — it was GF2-degenerate on the
// diagonal: xi ^ (yi&15) collapses to one bank when xi == yi.)
//
// Ownership is EXACT (unchanged since R8): band p owns yv = y+1 in
// [lo_p, hi_p), integer float bounds, tested on the SAME fmaf(tf,ca,ys1)
// everywhere; monotone yv(t): conservative analytic entry/exit + exact scans
// -> branchless counted loop; exit-scan start clamped to txhi+1 so all
// counted iterations are in-band AND in-window (every smem access staged).
// Guard-shifted coords xv = x+5 (trunc; eps<0 -> zero guard cols), yv = y+1.

#define B_ 8
#define N_ 256
#define A_ 180

constexpr int PAIRS      = A_ / 2;            // 90
constexpr int BAND       = 31;
constexpr int PHASES     = 9;                 // ceil(257/31)
constexpr int SMAX       = 287;               // max candidate stride
constexpr int TROWS      = 32;                // row-pairs: covers BAND+1 rows
constexpr int SMEM_BYTES = TROWS * SMAX * 8;  // 73,472 B -> 3 CTAs/SM
constexpr int NBLK       = B_ * PAIRS * PHASES;   // 6480

__device__ float g_partial[NBLK * 512];       // 13.3 MB static scratch

// ---- packed f32x2 helpers (sm_103a FFMA2/FADD2 via PTX) ----
typedef unsigned long long u64;
__device__ __forceinline__ u64 pk2(float lo, float hi) {
    u64 r; asm("mov.b64 %0, {%1, %2};" : "=l"(r) : "f"(lo), "f"(hi)); return r;
}
__device__ __forceinline__ void upk2(u64 v, float& lo, float& hi) {
    asm("mov.b64 {%0, %1}, %2;" : "=f"(lo), "=f"(hi) : "l"(v));
}
__device__ __forceinline__ u64 fma2(u64 a, u64 b, u64 c) {
    u64 d; asm("fma.rn.f32x2 %0, %1, %2, %3;" : "=l"(d) : "l"(a), "l"(b), "l"(c));
    return d;
}
__device__ __forceinline__ u64 add2(u64 a, u64 b) {
    u64 d; asm("add.rn.f32x2 %0, %1, %2;" : "=l"(d) : "l"(a), "l"(b));
    return d;
}

// Bank-conflict badness of stride S for one angle: per-lane address step is
// d = S*sa + ca; small distance to multiples of 16 (full collapse), 8, or
// odd multiples of 4 means high conflict degree. Larger score = better.
__device__ __forceinline__ float stride_score(float S, float sa, float ca) {
    float d  = fmaf(S, sa, ca);
    float u0 = d * (1.0f / 16.0f);
    float d0 = fabsf(u0 - rintf(u0)) * 16.0f;          // dist to 0 mod 16
    float u8 = (d - 8.0f) * (1.0f / 16.0f);
    float d8 = fabsf(u8 - rintf(u8)) * 16.0f;          // dist to 8 mod 16
    float u4 = (d - 4.0f) * (1.0f / 8.0f);
    float d4 = fabsf(u4 - rintf(u4)) * 8.0f;           // dist to 4 mod 8
    return fminf(d0, fminf(1.5f * d8, 3.0f * d4));
}

__global__ __launch_bounds__(512, 3)
void radon_phase_kernel(const float* __restrict__ imgs,
                        const float* __restrict__ angles)
{
    extern __shared__ float2 tile[];

    const int tid  = threadIdx.x;
    const int blk  = blockIdx.x;
    const int p    = blk % PHASES;
    const int bp   = blk / PHASES;            // b*PAIRS + pair
    const int b    = bp / PAIRS;
    const int pr   = bp - b * PAIRS;
    const int al   = tid >> 8;                // which angle of the pair
    const int warp = tid >> 5;
    const int lane = tid & 31;

    // ---- block-uniform stride selection from the pair's two angles ----
    const float angA = angles[pr * 2];
    const float angB = angles[pr * 2 + 1];
    const float saA = sinf(angA), caA = cosf(angA);
    const float saB = sinf(angB), caB = cosf(angB);
    int   S  = 287;
    float bs = fminf(stride_score(287.0f, saA, caA),
                     stride_score(287.0f, saB, caB));
    {
        float sc = fminf(stride_score(281.0f, saA, caA),
                         stride_score(281.0f, saB, caB));
        if (sc > bs) { bs = sc; S = 281; }
        sc = fminf(stride_score(273.0f, saA, caA),
                   stride_score(273.0f, saB, caB));
        if (sc > bs) { bs = sc; S = 273; }
    }
    const float Sf = (float)S;

    const float ca  = al ? caB : caA;
    const float sa  = al ? saB : saA;
    const float sf  = (float)(tid & 255) - 127.5f;
    const float xs  = fmaf(sf, ca, 127.5f);
    const float xs5 = xs + 5.0f;              // guard-shifted x origin
    const float ys1 = fmaf(sf, sa, 127.5f) + 1.0f;   // guard-shifted y origin
    const float nsa = -sa;
    const bool  up  = (ca >= 0.0f);           // yv non-decreasing in t?

    // yv endpoints (same fmaf form as the loop) for exact band pre-check
    const float yA    = fmaf(-127.5f, ca, ys1);
    const float yB    = fmaf( 127.5f, ca, ys1);
    const float yvmin = fminf(yA, yB);
    const float yvmax = fmaxf(yA, yB);

    // Owned band in yv space: floor(yv) in [lo, hi-1].
    // p=0: y0i in [-1,30] -> yv in [0,32).
    // p>0: y0i in [31p, 31p+30] -> yv in [31p+1, 31p+32). Exact int bounds.
    const float lo = (p == 0) ? 0.0f : (float)(BAND * p + 1);
    const float hi = (float)(BAND * p + 32);

    // block-wide empty-band early out (skip staging entirely)
    const bool hit = (yvmax >= lo) & (yvmin < hi);
    if (!__syncthreads_or(hit)) {
        g_partial[blk * 512 + tid] = 0.0f;
        return;
    }

    // ---- stage row-pair tile with runtime stride S:
    // tile[r*S + c] = (img[base+r][c-5], img[base+r+1][c-5])
    const int base = BAND * p - 1;            // image row of tile row r=0 (.x)
    const float* __restrict__ img = imgs + b * N_ * N_;
    for (int r = warp; r < TROWS; r += 16) {
        const int ir0 = base + r;
        const int ir1 = ir0 + 1;
        const bool v0ok = (unsigned)ir0 < (unsigned)N_;
        const bool v1ok = (unsigned)ir1 < (unsigned)N_;
        const float* s0 = img + ir0 * N_;
        const float* s1 = img + ir1 * N_;
        float2* dst = tile + r * S;
        for (int c = lane; c < S; c += 32) {
            int ic = c - 5;
            bool cin = (unsigned)ic < (unsigned)N_;
            float v0 = (v0ok && cin) ? s0[ic] : 0.0f;
            float v1 = (v1ok && cin) ? s1[ic] : 0.0f;
            dst[c] = make_float2(v0, v1);
        }
    }
    __syncthreads();

    float acc = 0.0f;

    if (hit) {
        // analytic helpers (conservative only; exactness from scans)
        const float inv_ca = 1.0f / ((ca == 0.0f) ? 1e-30f : ca);
        const float inv_sa = 1.0f / ((sa == 0.0f) ? 1e-30f : sa);

        // x-window: x outside (-3,259) padded +-2 -> sampled cols are zero
        // guards -> exactly 0. Inside: xv = x+5 in (-0.01, 266.01), so
        // xi in [0,266], xi+1 <= 267 < 273 <= S: all staged.
        float tca = (xs + 3.0f)   * inv_sa;
        float tcb = (xs - 259.0f) * inv_sa;
        const int txlo = (int)fmaxf(floorf(fminf(tca, tcb) + 127.5f) - 2.0f, 0.0f);
        const int txhi = (int)fminf(ceilf (fmaxf(tca, tcb) + 127.5f) + 2.0f, 255.0f);

        // conservative analytic entry (pad -2, never late), exact entry scan
        const float Lb = up ? lo : hi;
        float t_ent = fmaf(Lb - ys1, inv_ca, 127.5f);
        int t = max((int)fmaxf(fminf(floorf(t_ent) - 2.0f, 255.0f), 0.0f), txlo);
        float tf = (float)t - 127.5f;
        for (; t <= txhi; ++t, tf += 1.0f) {
            float yv = fmaf(tf, ca, ys1);
            if (up ? (yv >= lo) : (yv < hi)) break;
        }

        int n = 0;
        if (t <= txhi) {
            // conservative analytic exit, exact exit scan; start clamped to
            // txhi+1 (in float, before the int cast) so window-limited rays
            // count exactly txhi+1-t iterations (R8 fix).
            const float Ub = up ? hi : lo;
            float t_xt = fmaf(Ub - ys1, inv_ca, 127.5f);
            float te_f = fmaxf(fminf(floorf(t_xt) - 2.0f, (float)(txhi + 1)),
                               (float)t);
            int te = (int)te_f;
            float tfe = (float)te - 127.5f;
            for (; te <= txhi; ++te, tfe += 1.0f) {
                float yv = fmaf(tfe, ca, ys1);
                if (up ? (yv >= hi) : (yv < lo)) break;   // first t past band
            }
            n = te - t;     // owned iterations: t .. te-1 (in-band, in-window)
        }

        // fold band row offset into the base pointer: tile row = yi - 31p
        const u64* __restrict__ tb64 =
            reinterpret_cast<const u64*>(tile) - (BAND * p) * S;

        const u64 CANSA = pk2(ca, nsa);       // (ca, -sa)
        const u64 YXS   = pk2(ys1, xs5);      // (y origin, x origin)
        const u64 ONE2  = pk2(1.0f, 1.0f);
        const u64 NEG1  = pk2(-1.0f, -1.0f);
        u64 tf2 = pk2(tf, tf);

        #pragma unroll 4
        for (int k = 0; k < n; ++k) {
            u64 yx = fma2(tf2, CANSA, YXS);   // (yv, xv) — bitwise == scalar
            float yv, xv; upk2(yx, yv, xv);
            float fy = truncf(yv);            // yv >= 0 in-band: trunc == floor
            float fx = truncf(xv);            // eps<0 -> col 0 zero guard
            u64 wyx = fma2(pk2(fy, fx), NEG1, yx);   // (wy, wx), exact
            float wy, wx; upk2(wyx, wy, wx);
            int idx = (int)fmaf(fy, Sf, fx);  // exact (integer prods < 2^24)

            u64 v0 = tb64[idx];               // (a00, a10)
            u64 v1 = tb64[idx + 1];           // (a01, a11)

            u64 d = fma2(v0, NEG1, v1);       // (a01-a00, a11-a10)
            u64 h = fma2(pk2(wx, wx), d, v0); // (h0, h1)
            float h0, h1; upk2(h, h0, h1);
            acc += fmaf(wy, h1 - h0, h0);

            tf2 = add2(tf2, ONE2);
        }
    }

    g_partial[blk * 512 + tid] = acc;
}

// Kernel 2: out[b, 2*pr+al, s] = sum_p partial[((b*90+pr)*9+p)*512 + al*256 + s]
__global__ __launch_bounds__(256)
void radon_reduce_kernel(float* __restrict__ out)
{
    const int o  = blockIdx.x * 256 + threadIdx.x;   // 368,640 outputs
    const int s  = o & 255;
    const int ba = o >> 8;
    const int a  = ba % A_;
    const int b  = ba / A_;
    const int pr = a >> 1;
    const int al = a & 1;

    const float* p = g_partial + ((b * PAIRS + pr) * PHASES) * 512 + al * 256 + s;
    float acc = 0.0f;
    #pragma unroll
    for (int k = 0; k < PHASES; ++k) acc += p[k * 512];
    out[o] = acc;
}

extern "C" void kernel_launch(void* const* d_in, const int* in_sizes, int n_in,
                              void* d_out, int out_size)
{
    const float* imgs   = (const float*)d_in[0];
    const float* angles = (const float*)d_in[1];
    float*       out    = (float*)d_out;

    cudaFuncSetAttribute(radon_phase_kernel,
                         cudaFuncAttributeMaxDynamicSharedMemorySize, SMEM_BYTES);

    radon_phase_kernel<<<NBLK, 512, SMEM_BYTES>>>(imgs, angles);
    radon_reduce_kernel<<<(B_ * A_ * N_) / 256, 256>>>(out);
}

// round 17
// speedup vs baseline: 1.4343x; 1.0006x over previous
#include <cuda_runtime.h>

// Radon forward projection, phase-split + row-pair-float2 + PER-BLOCK STRIDE.
// out[b,a,s] = sum_t bilinear(imgs[b], x(s,t), y(s,t)),
// x = s*cos - t*sin + c ; y = s*sin + t*cos + c ; c = 127.5.
//
// Kernel 1: block = (b, angle-pair, phase), 6480 blocks, 512 threads
// (2 angles x 256 detectors). Phase p owns y0i in a 31-row band (32 for p0).
// Tile rows are float2 ROW PAIRS -> 2x LDS.64 per sample. 73.5 KB smem ->
// 3 CTAs/SM. Inner loop identical to the proven R11 kernel.
//
// CONFLICT FIX v2: bank conflicts occur only when the per-lane address step
// d = S*sa + ca is within ~1 of a multiple of 16 (or ~0.5 of 8, ~0.3 of 4
// mod 8) — a sparse, angle-specific set. The row stride S is therefore chosen
// PER BLOCK from {287, 281, 273} (all odd, >= 268 so every accessed column
// (<=267) is staged, <= 287 so the smem allocation fits): each block scores
// both of its angles for each candidate and takes the argmax. The choice is
// block-uniform and deterministic; staging and the reader derive addresses
// from the same stride register, so this is correctness-neutral. The inner
// loop cost is unchanged: idx = (int)fmaf(fy, Sf, fx) merely swaps an
// immediate for a register operand (exact for any integer stride: products
// < 2^24). (R14's XOR swizzle is reverted — it was GF2-degenerate on the
// diagonal: xi ^ (yi&15) collapses to one bank when xi == yi.)
//
// Ownership is EXACT (unchanged since R8): band p owns yv = y+1 in
// [lo_p, hi_p), integer float bounds, tested on the SAME fmaf(tf,ca,ys1)
// everywhere; monotone yv(t): conservative analytic entry/exit + exact scans
// -> branchless counted loop; exit-scan start clamped to txhi+1 so all
// counted iterations are in-band AND in-window (every smem access staged).
// Guard-shifted coords xv = x+5 (trunc; eps<0 -> zero guard cols), yv = y+1.

#define B_ 8
#define N_ 256
#define A_ 180

constexpr int PAIRS      = A_ / 2;            // 90
constexpr int BAND       = 31;
constexpr int PHASES     = 9;                 // ceil(257/31)
constexpr int SMAX       = 287;               // max candidate stride
constexpr int TROWS      = 32;                // row-pairs: covers BAND+1 rows
constexpr int SMEM_BYTES = TROWS * SMAX * 8;  // 73,472 B -> 3 CTAs/SM
constexpr int NBLK       = B_ * PAIRS * PHASES;   // 6480

__device__ float g_partial[NBLK * 512];       // 13.3 MB static scratch

// ---- packed f32x2 helpers (sm_103a FFMA2/FADD2 via PTX) ----
typedef unsigned long long u64;
__device__ __forceinline__ u64 pk2(float lo, float hi) {
    u64 r; asm("mov.b64 %0, {%1, %2};" : "=l"(r) : "f"(lo), "f"(hi)); return r;
}
__device__ __forceinline__ void upk2(u64 v, float& lo, float& hi) {
    asm("mov.b64 {%0, %1}, %2;" : "=f"(lo), "=f"(hi) : "l"(v));
}
__device__ __forceinline__ u64 fma2(u64 a, u64 b, u64 c) {
    u64 d; asm("fma.rn.f32x2 %0, %1, %2, %3;" : "=l"(d) : "l"(a), "l"(b), "l"(c));
    return d;
}
__device__ __forceinline__ u64 add2(u64 a, u64 b) {
    u64 d; asm("add.rn.f32x2 %0, %1, %2;" : "=l"(d) : "l"(a), "l"(b));
    return d;
}

// Bank-conflict badness of stride S for one angle: per-lane address step is
// d = S*sa + ca; small distance to multiples of 16 (full collapse), 8, or
// odd multiples of 4 means high conflict degree. Larger score = better.
__device__ __forceinline__ float stride_score(float S, float sa, float ca) {
    float d  = fmaf(S, sa, ca);
    float u0 = d * (1.0f / 16.0f);
    float d0 = fabsf(u0 - rintf(u0)) * 16.0f;          // dist to 0 mod 16
    float u8 = (d - 8.0f) * (1.0f / 16.0f);
    float d8 = fabsf(u8 - rintf(u8)) * 16.0f;          // dist to 8 mod 16
    float u4 = (d - 4.0f) * (1.0f / 8.0f);
    float d4 = fabsf(u4 - rintf(u4)) * 8.0f;           // dist to 4 mod 8
    return fminf(d0, fminf(1.5f * d8, 3.0f * d4));
}

__global__ __launch_bounds__(512, 3)
void radon_phase_kernel(const float* __restrict__ imgs,
                        const float* __restrict__ angles)
{
    extern __shared__ float2 tile[];

    const int tid  = threadIdx.x;
    const int blk  = blockIdx.x;
    const int p    = blk % PHASES;
    const int bp   = blk / PHASES;            // b*PAIRS + pair
    const int b    = bp / PAIRS;
    const int pr   = bp - b * PAIRS;
    const int al   = tid >> 8;                // which angle of the pair
    const int warp = tid >> 5;
    const int lane = tid & 31;

    // ---- block-uniform stride selection from the pair's two angles ----
    const float angA = angles[pr * 2];
    const float angB = angles[pr * 2 + 1];
    const float saA = sinf(angA), caA = cosf(angA);
    const float saB = sinf(angB), caB = cosf(angB);
    int   S  = 287;
    float bs = fminf(stride_score(287.0f, saA, caA),
                     stride_score(287.0f, saB, caB));
    {
        float sc = fminf(stride_score(281.0f, saA, caA),
                         stride_score(281.0f, saB, caB));
        if (sc > bs) { bs = sc; S = 281; }
        sc = fminf(stride_score(273.0f, saA, caA),
                   stride_score(273.0f, saB, caB));
        if (sc > bs) { bs = sc; S = 273; }
    }
    const float Sf = (float)S;

    const float ca  = al ? caB : caA;
    const float sa  = al ? saB : saA;
    const float sf  = (float)(tid & 255) - 127.5f;
    const float xs  = fmaf(sf, ca, 127.5f);
    const float xs5 = xs + 5.0f;              // guard-shifted x origin
    const float ys1 = fmaf(sf, sa, 127.5f) + 1.0f;   // guard-shifted y origin
    const float nsa = -sa;
    const bool  up  = (ca >= 0.0f);           // yv non-decreasing in t?

    // yv endpoints (same fmaf form as the loop) for exact band pre-check
    const float yA    = fmaf(-127.5f, ca, ys1);
    const float yB    = fmaf( 127.5f, ca, ys1);
    const float yvmin = fminf(yA, yB);
    const float yvmax = fmaxf(yA, yB);

    // Owned band in yv space: floor(yv) in [lo, hi-1].
    // p=0: y0i in [-1,30] -> yv in [0,32).
    // p>0: y0i in [31p, 31p+30] -> yv in [31p+1, 31p+32). Exact int bounds.
    const float lo = (p == 0) ? 0.0f : (float)(BAND * p + 1);
    const float hi = (float)(BAND * p + 32);

    // block-wide empty-band early out (skip staging entirely)
    const bool hit = (yvmax >= lo) & (yvmin < hi);
    if (!__syncthreads_or(hit)) {
        g_partial[blk * 512 + tid] = 0.0f;
        return;
    }

    // ---- stage row-pair tile with runtime stride S:
    // tile[r*S + c] = (img[base+r][c-5], img[base+r+1][c-5])
    const int base = BAND * p - 1;            // image row of tile row r=0 (.x)
    const float* __restrict__ img = imgs + b * N_ * N_;
    for (int r = warp; r < TROWS; r += 16) {
        const int ir0 = base + r;
        const int ir1 = ir0 + 1;
        const bool v0ok = (unsigned)ir0 < (unsigned)N_;
        const bool v1ok = (unsigned)ir1 < (unsigned)N_;
        const float* s0 = img + ir0 * N_;
        const float* s1 = img + ir1 * N_;
        float2* dst = tile + r * S;
        for (int c = lane; c < S; c += 32) {
            int ic = c - 5;
            bool cin = (unsigned)ic < (unsigned)N_;
            float v0 = (v0ok && cin) ? s0[ic] : 0.0f;
            float v1 = (v1ok && cin) ? s1[ic] : 0.0f;
            dst[c] = make_float2(v0, v1);
        }
    }
    __syncthreads();

    float acc = 0.0f;

    if (hit) {
        // analytic helpers (conservative only; exactness from scans)
        const float inv_ca = 1.0f / ((ca == 0.0f) ? 1e-30f : ca);
        const float inv_sa = 1.0f / ((sa == 0.0f) ? 1e-30f : sa);

        // x-window: x outside (-3,259) padded +-2 -> sampled cols are zero
        // guards -> exactly 0. Inside: xv = x+5 in (-0.01, 266.01), so
        // xi in [0,266], xi+1 <= 267 < 273 <= S: all staged.
        float tca = (xs + 3.0f)   * inv_sa;
        float tcb = (xs - 259.0f) * inv_sa;
        const int txlo = (int)fmaxf(floorf(fminf(tca, tcb) + 127.5f) - 2.0f, 0.0f);
        const int txhi = (int)fminf(ceilf (fmaxf(tca, tcb) + 127.5f) + 2.0f, 255.0f);

        // conservative analytic entry (pad -2, never late), exact entry scan
        const float Lb = up ? lo : hi;
        float t_ent = fmaf(Lb - ys1, inv_ca, 127.5f);
        int t = max((int)fmaxf(fminf(floorf(t_ent) - 2.0f, 255.0f), 0.0f), txlo);
        float tf = (float)t - 127.5f;
        for (; t <= txhi; ++t, tf += 1.0f) {
            float yv = fmaf(tf, ca, ys1);
            if (up ? (yv >= lo) : (yv < hi)) break;
        }

        int n = 0;
        if (t <= txhi) {
            // conservative analytic exit, exact exit scan; start clamped to
            // txhi+1 (in float, before the int cast) so window-limited rays
            // count exactly txhi+1-t iterations (R8 fix).
            const float Ub = up ? hi : lo;
            float t_xt = fmaf(Ub - ys1, inv_ca, 127.5f);
            float te_f = fmaxf(fminf(floorf(t_xt) - 2.0f, (float)(txhi + 1)),
                               (float)t);
            int te = (int)te_f;
            float tfe = (float)te - 127.5f;
            for (; te <= txhi; ++te, tfe += 1.0f) {
                float yv = fmaf(tfe, ca, ys1);
                if (up ? (yv >= hi) : (yv < lo)) break;   // first t past band
            }
            n = te - t;     // owned iterations: t .. te-1 (in-band, in-window)
        }

        // fold band row offset into the base pointer: tile row = yi - 31p
        const u64* __restrict__ tb64 =
            reinterpret_cast<const u64*>(tile) - (BAND * p) * S;

        const u64 CANSA = pk2(ca, nsa);       // (ca, -sa)
        const u64 YXS   = pk2(ys1, xs5);      // (y origin, x origin)
        const u64 ONE2  = pk2(1.0f, 1.0f);
        const u64 NEG1  = pk2(-1.0f, -1.0f);
        u64 tf2 = pk2(tf, tf);

        #pragma unroll 4
        for (int k = 0; k < n; ++k) {
            u64 yx = fma2(tf2, CANSA, YXS);   // (yv, xv) — bitwise == scalar
            float yv, xv; upk2(yx, yv, xv);
            float fy = truncf(yv);            // yv >= 0 in-band: trunc == floor
            float fx = truncf(xv);            // eps<0 -> col 0 zero guard
            u64 wyx = fma2(pk2(fy, fx), NEG1, yx);   // (wy, wx), exact
            float wy, wx; upk2(wyx, wy, wx);
            int idx = (int)fmaf(fy, Sf, fx);  // exact (integer prods < 2^24)

            u64 v0 = tb64[idx];               // (a00, a10)
            u64 v1 = tb64[idx + 1];           // (a01, a11)

            u64 d = fma2(v0, NEG1, v1);       // (a01-a00, a11-a10)
            u64 h = fma2(pk2(wx, wx), d, v0); // (h0, h1)
            float h0, h1; upk2(h, h0, h1);
            acc += fmaf(wy, h1 - h0, h0);

            tf2 = add2(tf2, ONE2);
        }
    }

    g_partial[blk * 512 + tid] = acc;
}

// Kernel 2: out[b, 2*pr+al, s] = sum_p partial[((b*90+pr)*9+p)*512 + al*256 + s]
__global__ __launch_bounds__(256)
void radon_reduce_kernel(float* __restrict__ out)
{
    const int o  = blockIdx.x * 256 + threadIdx.x;   // 368,640 outputs
    const int s  = o & 255;
    const int ba = o >> 8;
    const int a  = ba % A_;
    const int b  = ba / A_;
    const int pr = a >> 1;
    const int al = a & 1;

    const float* p = g_partial + ((b * PAIRS + pr) * PHASES) * 512 + al * 256 + s;
    float acc = 0.0f;
    #pragma unroll
    for (int k = 0; k < PHASES; ++k) acc += p[k * 512];
    out[o] = acc;
}

extern "C" void kernel_launch(void* const* d_in, const int* in_sizes, int n_in,
                              void* d_out, int out_size)
{
    const float* imgs   = (const float*)d_in[0];
    const float* angles = (const float*)d_in[1];
    float*       out    = (float*)d_out;

    cudaFuncSetAttribute(radon_phase_kernel,
                         cudaFuncAttributeMaxDynamicSharedMemorySize, SMEM_BYTES);

    radon_phase_kernel<<<NBLK, 512, SMEM_BYTES>>>(imgs, angles);
    radon_reduce_kernel<<<(B_ * A_ * N_) / 256, 256>>>(out);
}